// round 2
// baseline (speedup 1.0000x reference)
#include <cuda_runtime.h>
#include <cstdint>

#define NTOK 60000
#define DIM 128
#define NHEAD 8
#define HDIM 16
#define DFF 256
#define NLAYER 12
#define NY 400
#define NX 400
#define NPIX (2*NY*NX)

// ---------------- scratch (static device globals; no runtime alloc) ----------------
__device__ float g_feat[NTOK * DIM];
__device__ float g_pos[2][NTOK * DIM];
__device__ float g_qk[NTOK * 256];        // per-level q|k (ld 256)
__device__ float g_val[NTOK * DIM];
__device__ float g_oatt[NTOK * DIM];      // per-level attention out (pre-proj)
__device__ float g_attn[NTOK * DIM];      // scattered attention out over all tokens
__device__ float g_hbuf[NTOK * DFF];
__device__ float g_tmp[NTOK * DIM];
__device__ float g_canvas[(size_t)NPIX * DIM];   // NHWC
__device__ float g_conv1[(size_t)NPIX * DIM];    // NHWC
__device__ float g_wt[2 * 9 * DIM * DIM];        // [cv][tap*128+ci][o]

// ---------------- positional embedding ----------------
__global__ void pos_kernel(const float* __restrict__ ciw, float* __restrict__ pos) {
    int n = blockIdx.x;
    int t = threadIdx.x;          // 0..127
    int axis = t >> 6;            // 0: x, 1: y
    int d = t & 63;
    int j = d >> 1;
    float xy = ciw[n * 2 + axis] - 6.0f;
    float inv = powf(10000.0f, (float)j / 32.0f);
    float e = xy / inv;
    pos[(size_t)n * DIM + t] = (d & 1) ? cosf(e) : sinf(e);
}

// ---------------- generic tiled SGEMM: C = A @ W^T + bias (+epilogues) -------------
// A: [M,K] rows optionally gathered via gidx (and summed with A2 rows, same gather)
// W: [Nc,K] row-major. C: [M,Nc], rows optionally scattered via sidx.
template<bool GATHER_A, bool ADD_A2, bool GELU_EP, bool RESID, bool SCATTER_C>
__global__ void __launch_bounds__(256) gemm_kernel(
    const float* __restrict__ A, const float* __restrict__ A2,
    const int* __restrict__ gidx,
    const float* __restrict__ W, const float* __restrict__ bias,
    const float* __restrict__ resid, const int* __restrict__ sidx,
    float* __restrict__ C, int M, int K, int Nc)
{
    __shared__ float As[16][68];
    __shared__ float Bs[16][68];
    int tid = threadIdx.x;
    int col0 = blockIdx.x * 64;
    int row0 = blockIdx.y * 64;
    int tx = tid & 15, ty = tid >> 4;
    int lk = tid & 15;        // k within chunk
    int lr = tid >> 4;        // row/col group base
    float acc[4][4] = {};
    for (int k0 = 0; k0 < K; k0 += 16) {
        #pragma unroll
        for (int i = 0; i < 4; i++) {
            int m = lr + i * 16;
            int gm = row0 + m;
            float vA = 0.0f;
            if (gm < M) {
                int src = GATHER_A ? gidx[gm] : gm;
                size_t off = (size_t)src * K + k0 + lk;
                vA = A[off];
                if (ADD_A2) vA += A2[off];
            }
            As[lk][m] = vA;
        }
        #pragma unroll
        for (int i = 0; i < 4; i++) {
            int n = lr + i * 16;
            Bs[lk][n] = W[(size_t)(col0 + n) * K + k0 + lk];
        }
        __syncthreads();
        #pragma unroll
        for (int kk = 0; kk < 16; kk++) {
            float a[4], b[4];
            #pragma unroll
            for (int i = 0; i < 4; i++) a[i] = As[kk][ty * 4 + i];
            #pragma unroll
            for (int j = 0; j < 4; j++) b[j] = Bs[kk][tx * 4 + j];
            #pragma unroll
            for (int i = 0; i < 4; i++)
                #pragma unroll
                for (int j = 0; j < 4; j++)
                    acc[i][j] += a[i] * b[j];
        }
        __syncthreads();
    }
    #pragma unroll
    for (int i = 0; i < 4; i++) {
        int m = row0 + ty * 4 + i;
        if (m >= M) continue;
        int r = SCATTER_C ? sidx[m] : m;
        #pragma unroll
        for (int j = 0; j < 4; j++) {
            int n = col0 + tx * 4 + j;
            float c = acc[i][j] + bias[n];
            if (GELU_EP) c = 0.5f * c * (1.0f + erff(c * 0.70710678118654752f));
            if (RESID)   c += resid[(size_t)m * Nc + n];
            C[(size_t)r * Nc + n] = c;
        }
    }
}

// ---------------- windowed attention: one block per (window, head) ----------------
// QK: [M,256] (q at +0, k at +128), V: [M,128], O: [M,128]. cap <= 100.
__global__ void __launch_bounds__(128) attn_kernel(
    const float* __restrict__ QK, const float* __restrict__ V,
    float* __restrict__ O, int M, int cap)
{
    __shared__ float Ks[100 * 16];
    __shared__ float Vs[100 * 16];
    __shared__ float sred[4][32][16];
    int w = blockIdx.x, h = blockIdx.y;
    int base = w * cap;
    int nval = min(cap, M - base);
    int tid = threadIdx.x, lane = tid & 31, warp = tid >> 5;
    for (int i = tid; i < nval * 16; i += 128) {
        int t = i >> 4, d = i & 15;
        Ks[t * 16 + d] = QK[(size_t)(base + t) * 256 + 128 + h * 16 + d];
        Vs[t * 16 + d] = V[(size_t)(base + t) * 128 + h * 16 + d];
    }
    __syncthreads();
    for (int r = warp; r < nval; r += 4) {
        float q[16];
        #pragma unroll
        for (int d = 0; d < 16; d++) q[d] = QK[(size_t)(base + r) * 256 + h * 16 + d];
        float s[4];
        float mx = -1e30f;
        #pragma unroll
        for (int jj = 0; jj < 4; jj++) {
            int key = lane + jj * 32;
            float sc = -1e30f;
            if (key < nval) {
                sc = 0.0f;
                #pragma unroll
                for (int d = 0; d < 16; d++) sc += q[d] * Ks[key * 16 + d];
                sc *= 0.25f;
            }
            s[jj] = sc;
            mx = fmaxf(mx, sc);
        }
        #pragma unroll
        for (int o = 16; o; o >>= 1) mx = fmaxf(mx, __shfl_xor_sync(0xffffffffu, mx, o));
        float l = 0.0f;
        float acc[16] = {};
        #pragma unroll
        for (int jj = 0; jj < 4; jj++) {
            int key = lane + jj * 32;
            if (key < nval) {
                float p = __expf(s[jj] - mx);
                l += p;
                #pragma unroll
                for (int d = 0; d < 16; d++) acc[d] += p * Vs[key * 16 + d];
            }
        }
        #pragma unroll
        for (int o = 16; o; o >>= 1) l += __shfl_xor_sync(0xffffffffu, l, o);
        #pragma unroll
        for (int d = 0; d < 16; d++) sred[warp][lane][d] = acc[d];
        __syncwarp();
        if (lane < 16) {
            float o = 0.0f;
            #pragma unroll
            for (int l2 = 0; l2 < 32; l2++) o += sred[warp][l2][lane];
            O[(size_t)(base + r) * 128 + h * 16 + lane] = o / l;
        }
        __syncwarp();
    }
}

// ---------------- layernorm (optional residual add), warp-per-row ----------------
__global__ void __launch_bounds__(256) ln_kernel(
    const float* __restrict__ X, const float* __restrict__ X2,
    const float* __restrict__ g, const float* __restrict__ b,
    float* __restrict__ Y, int M)
{
    int row = blockIdx.x * 8 + (threadIdx.x >> 5);
    if (row >= M) return;
    int lane = threadIdx.x & 31;
    float v[4];
    #pragma unroll
    for (int i = 0; i < 4; i++) {
        int c = lane + i * 32;
        float t = X[(size_t)row * DIM + c];
        if (X2) t += X2[(size_t)row * DIM + c];
        v[i] = t;
    }
    float s = v[0] + v[1] + v[2] + v[3];
    #pragma unroll
    for (int o = 16; o; o >>= 1) s += __shfl_xor_sync(0xffffffffu, s, o);
    float mu = s * (1.0f / 128.0f);
    float vs = 0.0f;
    #pragma unroll
    for (int i = 0; i < 4; i++) { float d = v[i] - mu; vs += d * d; }
    #pragma unroll
    for (int o = 16; o; o >>= 1) vs += __shfl_xor_sync(0xffffffffu, vs, o);
    float inv = rsqrtf(vs * (1.0f / 128.0f) + 1e-5f);
    #pragma unroll
    for (int i = 0; i < 4; i++) {
        int c = lane + i * 32;
        Y[(size_t)row * DIM + c] = (v[i] - mu) * inv * g[c] + b[c];
    }
}

// ---------------- BEV scatter (NHWC canvas) ----------------
__global__ void scatter_kernel(const float* __restrict__ feat,
                               const int* __restrict__ coors,
                               float* __restrict__ canvas)
{
    int i = blockIdx.x;
    int c = threadIdx.x;
    int b = coors[i * 4 + 0];
    int y = coors[i * 4 + 2];
    int x = coors[i * 4 + 3];
    canvas[(((size_t)b * NY + y) * NX + x) * DIM + c] = feat[(size_t)i * DIM + c];
}

// ---------------- conv weight transpose: [cv][o][i][ky][kx] -> [cv][(ky*3+kx)*128+i][o]
__global__ void prep_wt_kernel(const float* __restrict__ cw, float* __restrict__ wt) {
    int idx = blockIdx.x * 256 + threadIdx.x;
    if (idx >= 2 * 9 * DIM * DIM) return;
    int cv = idx / (9 * DIM * DIM);
    int r = idx % (9 * DIM * DIM);
    int k = r / DIM, o = r % DIM;
    int tap = k / DIM, ci = k % DIM;
    int ky = tap / 3, kx = tap % 3;
    wt[idx] = cw[((((size_t)cv * DIM + o) * DIM + ci) * 3 + ky) * 3 + kx];
}

// ---------------- dilated 3x3 conv as implicit GEMM + BN(eval) + ReLU ----------------
// src NHWC [2,400,400,128]; Wt [1152,128]; dst NHWC (nchw=0) or NCHW (nchw=1)
__global__ void __launch_bounds__(256) conv_kernel(
    const float* __restrict__ src, const float* __restrict__ Wt,
    const float* __restrict__ bng, const float* __restrict__ bnb,
    const float* __restrict__ bnm, const float* __restrict__ bnv,
    float* __restrict__ dst, int nchw)
{
    __shared__ float As[16][68];
    __shared__ float Bs[16][68];
    int tid = threadIdx.x;
    int col0 = blockIdx.x * 64;
    int p0 = blockIdx.y * 64;
    int tx = tid & 15, ty = tid >> 4;
    int lk = tid & 15;
    int lr = tid >> 4;
    int nn = tid & 63, kq = tid >> 6;
    float acc[4][4] = {};
    for (int k0 = 0; k0 < 9 * DIM; k0 += 16) {
        int tap = k0 >> 7;
        int dy = ((tap / 3) - 1) * 2;
        int dx = ((tap % 3) - 1) * 2;
        int ci0 = k0 & 127;
        #pragma unroll
        for (int i = 0; i < 4; i++) {
            int m = lr + i * 16;
            int p = p0 + m;
            int b = p / (NY * NX);
            int rem = p % (NY * NX);
            int y = rem / NX, x = rem % NX;
            int yy = y + dy, xx = x + dx;
            float vA = 0.0f;
            if ((unsigned)yy < NY && (unsigned)xx < NX)
                vA = src[(((size_t)b * NY + yy) * NX + xx) * DIM + ci0 + lk];
            As[lk][m] = vA;
        }
        #pragma unroll
        for (int i = 0; i < 4; i++)
            Bs[kq + i * 4][nn] = Wt[(size_t)(k0 + kq + i * 4) * DIM + col0 + nn];
        __syncthreads();
        #pragma unroll
        for (int kk = 0; kk < 16; kk++) {
            float a[4], b[4];
            #pragma unroll
            for (int i = 0; i < 4; i++) a[i] = As[kk][ty * 4 + i];
            #pragma unroll
            for (int j = 0; j < 4; j++) b[j] = Bs[kk][tx * 4 + j];
            #pragma unroll
            for (int i = 0; i < 4; i++)
                #pragma unroll
                for (int j = 0; j < 4; j++)
                    acc[i][j] += a[i] * b[j];
        }
        __syncthreads();
    }
    #pragma unroll
    for (int i = 0; i < 4; i++) {
        int p = p0 + ty * 4 + i;
        int b = p / (NY * NX);
        int rem = p % (NY * NX);
        int y = rem / NX, x = rem % NX;
        #pragma unroll
        for (int j = 0; j < 4; j++) {
            int o = col0 + tx * 4 + j;
            float sc = bng[o] * rsqrtf(bnv[o] + 1e-3f);
            float c = (acc[i][j] - bnm[o]) * sc + bnb[o];
            c = fmaxf(c, 0.0f);
            if (nchw)
                dst[(((size_t)b * DIM + o) * NY + y) * NX + x] = c;
            else
                dst[(size_t)p * DIM + o] = c;
        }
    }
}

// ---------------- host launcher ----------------
extern "C" void kernel_launch(void* const* d_in, const int* in_sizes, int n_in,
                              void* d_out, int out_size) {
    const float* voxel_feat = (const float*)d_in[0];
    const int*   coors      = (const int*)d_in[1];
    const float* ciw0       = (const float*)d_in[2];
    const float* ciw1       = (const float*)d_in[3];
    const int*   vx00       = (const int*)d_in[4];
    const int*   vx01       = (const int*)d_in[6];
    const int*   vx10       = (const int*)d_in[8];
    const int*   vx11       = (const int*)d_in[10];
    const float* ipw        = (const float*)d_in[12];
    const float* ipb        = (const float*)d_in[13];
    const float* ow         = (const float*)d_in[14];
    const float* ob         = (const float*)d_in[15];
    const float* l1w        = (const float*)d_in[16];
    const float* l1b        = (const float*)d_in[17];
    const float* l2w        = (const float*)d_in[18];
    const float* l2b        = (const float*)d_in[19];
    const float* g1         = (const float*)d_in[20];
    const float* b1         = (const float*)d_in[21];
    const float* g2         = (const float*)d_in[22];
    const float* b2         = (const float*)d_in[23];
    const float* cw         = (const float*)d_in[24];
    const float* bng        = (const float*)d_in[25];
    const float* bnb        = (const float*)d_in[26];
    const float* bnm        = (const float*)d_in[27];
    const float* bnv        = (const float*)d_in[28];

    int ntok0  = in_sizes[4];
    int ntok1  = in_sizes[6];
    int ntok0b = in_sizes[8];
    int ntok1b = in_sizes[10];

    float *feat, *pos, *qk, *val, *oatt, *attn, *hbuf, *tmp, *canvas, *conv1, *wt;
    cudaGetSymbolAddress((void**)&feat,   g_feat);
    cudaGetSymbolAddress((void**)&pos,    g_pos);
    cudaGetSymbolAddress((void**)&qk,     g_qk);
    cudaGetSymbolAddress((void**)&val,    g_val);
    cudaGetSymbolAddress((void**)&oatt,   g_oatt);
    cudaGetSymbolAddress((void**)&attn,   g_attn);
    cudaGetSymbolAddress((void**)&hbuf,   g_hbuf);
    cudaGetSymbolAddress((void**)&tmp,    g_tmp);
    cudaGetSymbolAddress((void**)&canvas, g_canvas);
    cudaGetSymbolAddress((void**)&conv1,  g_conv1);
    cudaGetSymbolAddress((void**)&wt,     g_wt);

    cudaMemcpyAsync(feat, voxel_feat, (size_t)NTOK * DIM * sizeof(float),
                    cudaMemcpyDeviceToDevice);
    pos_kernel<<<NTOK, 128>>>(ciw0, pos);
    pos_kernel<<<NTOK, 128>>>(ciw1, pos + (size_t)NTOK * DIM);
    prep_wt_kernel<<<(2 * 9 * DIM * DIM + 255) / 256, 256>>>(cw, wt);

    for (int li = 0; li < NLAYER; li++) {
        int s = li & 1;
        const int* vv[2];
        int mm[2];
        if (s == 0) { vv[0] = vx00; vv[1] = vx01; mm[0] = ntok0;  mm[1] = ntok1; }
        else        { vv[0] = vx10; vv[1] = vx11; mm[0] = ntok0b; mm[1] = ntok1b; }
        int caps[2] = {25, 100};
        const float* posS = pos + (size_t)s * NTOK * DIM;
        const float* Wip  = ipw + (size_t)li * 384 * DIM;
        const float* Bip  = ipb + (size_t)li * 384;

        for (int lvl = 0; lvl < 2; lvl++) {
            int M = mm[lvl];
            const int* v = vv[lvl];
            dim3 gqk(256 / 64, (M + 63) / 64);
            gemm_kernel<true, true, false, false, false><<<gqk, 256>>>(
                feat, posS, v, Wip, Bip, nullptr, nullptr, qk, M, 128, 256);
            dim3 g128(128 / 64, (M + 63) / 64);
            gemm_kernel<true, false, false, false, false><<<g128, 256>>>(
                feat, nullptr, v, Wip + 256 * 128, Bip + 256, nullptr, nullptr,
                val, M, 128, 128);
            int nw = (M + caps[lvl] - 1) / caps[lvl];
            attn_kernel<<<dim3(nw, NHEAD), 128>>>(qk, val, oatt, M, caps[lvl]);
            gemm_kernel<false, false, false, false, true><<<g128, 256>>>(
                oatt, nullptr, nullptr, ow + (size_t)li * 128 * 128,
                ob + (size_t)li * 128, nullptr, v, attn, M, 128, 128);
        }
        ln_kernel<<<(NTOK + 7) / 8, 256>>>(feat, attn, g1 + li * 128, b1 + li * 128,
                                           feat, NTOK);
        dim3 gf1(DFF / 64, (NTOK + 63) / 64);
        gemm_kernel<false, false, true, false, false><<<gf1, 256>>>(
            feat, nullptr, nullptr, l1w + (size_t)li * DFF * DIM,
            l1b + (size_t)li * DFF, nullptr, nullptr, hbuf, NTOK, 128, DFF);
        dim3 gf2(DIM / 64, (NTOK + 63) / 64);
        gemm_kernel<false, false, false, true, false><<<gf2, 256>>>(
            hbuf, nullptr, nullptr, l2w + (size_t)li * DIM * DFF,
            l2b + (size_t)li * DIM, feat, nullptr, tmp, NTOK, DFF, 128);
        ln_kernel<<<(NTOK + 7) / 8, 256>>>(tmp, nullptr, g2 + li * 128, b2 + li * 128,
                                           feat, NTOK);
    }

    cudaMemsetAsync(canvas, 0, (size_t)NPIX * DIM * sizeof(float));
    scatter_kernel<<<NTOK, 128>>>(feat, coors, canvas);
    conv_kernel<<<dim3(DIM / 64, NPIX / 64), 256>>>(
        canvas, wt, bng, bnb, bnm, bnv, conv1, 0);
    conv_kernel<<<dim3(DIM / 64, NPIX / 64), 256>>>(
        conv1, wt + 9 * DIM * DIM, bng + 128, bnb + 128, bnm + 128, bnv + 128,
        (float*)d_out, 1);
}

// round 5
// speedup vs baseline: 1.5803x; 1.5803x over previous
#include <cuda_runtime.h>
#include <cstdint>

#define NTOK 60000
#define DIM 128
#define NHEAD 8
#define DFF 256
#define NLAYER 12
#define NY 400
#define NX 400
#define NPIX (2*NY*NX)

// ---------------- scratch ----------------
__device__ float g_feat[NTOK * DIM];
__device__ float g_fp[NTOK * DIM];        // feat + pos (per layer)
__device__ float g_pos[2][NTOK * DIM];
__device__ float g_qk[NTOK * 256];
__device__ float g_val[NTOK * DIM];
__device__ float g_oatt[NTOK * DIM];
__device__ float g_attn[NTOK * DIM];
__device__ float g_hbuf[NTOK * DFF];
__device__ float g_tmp[NTOK * DIM];
__device__ float g_canvas[(size_t)NPIX * DIM];   // NHWC
__device__ float g_conv1[(size_t)NPIX * DIM];    // NHWC
__device__ float g_wt[2 * 128 * 1152];           // [cv][o][tap*128+ci]

// ---------------- ptx helpers ----------------
__device__ __forceinline__ unsigned f2tf(float f) {
    unsigned u;
    asm("cvt.rna.tf32.f32 %0, %1;" : "=r"(u) : "f"(f));
    return u;
}
__device__ __forceinline__ void mma_tf32(float c[4], const unsigned a[4], const unsigned b[2]) {
    asm volatile(
        "mma.sync.aligned.m16n8k8.row.col.f32.tf32.tf32.f32 "
        "{%0,%1,%2,%3},{%4,%5,%6,%7},{%8,%9},{%0,%1,%2,%3};"
        : "+f"(c[0]), "+f"(c[1]), "+f"(c[2]), "+f"(c[3])
        : "r"(a[0]), "r"(a[1]), "r"(a[2]), "r"(a[3]), "r"(b[0]), "r"(b[1]));
}
__device__ __forceinline__ void cp16(unsigned dst, const void* src, bool pred) {
    int sz = pred ? 16 : 0;
    asm volatile("cp.async.cg.shared.global [%0], [%1], 16, %2;"
                 :: "r"(dst), "l"(src), "r"(sz));
}
__device__ __forceinline__ void cp_commit() { asm volatile("cp.async.commit_group;"); }
__device__ __forceinline__ void cp_wait0()  { asm volatile("cp.async.wait_group 0;" ::: "memory"); }

// ---------------- positional embedding ----------------
__global__ void pos_kernel(const float* __restrict__ ciw, float* __restrict__ pos) {
    int n = blockIdx.x;
    int t = threadIdx.x;
    int axis = t >> 6;
    int d = t & 63;
    int j = d >> 1;
    float xy = ciw[n * 2 + axis] - 6.0f;
    float inv = powf(10000.0f, (float)j / 32.0f);
    float e = xy / inv;
    pos[(size_t)n * DIM + t] = (d & 1) ? cosf(e) : sinf(e);
}

// ---------------- feat + pos ----------------
__global__ void addpos_kernel(const float* __restrict__ f, const float* __restrict__ p,
                              float* __restrict__ o) {
    size_t i = (size_t)blockIdx.x * 256 + threadIdx.x;
    float4 a = ((const float4*)f)[i];
    float4 b = ((const float4*)p)[i];
    a.x += b.x; a.y += b.y; a.z += b.z; a.w += b.w;
    ((float4*)o)[i] = a;
}

// ================= tf32 tensor-core GEMM =================
// C[M,Nc] = A[M,K] @ W[Nc,K]^T + bias; A rows optionally gathered, C rows
// optionally scattered; optional GELU / residual epilogues.
// Block tile 128x128x16, 256 threads (8 warps, 2x4 grid, warp tile 64x32),
// cp.async double buffered.
template<bool GATHER_A, bool GELU_EP, bool RESID, bool SCATTER_C>
__global__ void __launch_bounds__(256) gemm_tc(
    const float* __restrict__ A, const int* __restrict__ gidx,
    const float* __restrict__ W, const float* __restrict__ bias,
    const float* __restrict__ resid, const int* __restrict__ sidx,
    float* __restrict__ C, int M, int K, int Nc)
{
    __shared__ float As[2][128 * 20];
    __shared__ float Bs[2][128 * 20];
    int tid = threadIdx.x;
    int row0 = blockIdx.y * 128;
    int col0 = blockIdx.x * 128;
    int lane = tid & 31, wid = tid >> 5;
    int gid = lane >> 2, tq = lane & 3;
    int wm0 = (wid >> 2) * 64;     // 2 m-warps * 64 rows = 128
    int wn0 = (wid & 3) * 32;      // 4 n-warps * 32 cols = 128

    // loader: thread-fixed row + 2 segments of 4 floats (128 rows x 16 floats)
    int lr = tid & 127;
    int seg0 = (tid >> 7) * 2;
    int gm = row0 + lr;
    bool avalid = gm < M;
    int gmc = avalid ? gm : 0;
    const float* arow = A + (size_t)(GATHER_A ? gidx[gmc] : gmc) * K;
    const float* brow = W + (size_t)(col0 + lr) * K;
    unsigned sA0 = (unsigned)__cvta_generic_to_shared(&As[0][0]);
    unsigned sB0 = (unsigned)__cvta_generic_to_shared(&Bs[0][0]);
    unsigned dA = sA0 + lr * 80;   // 20 floats * 4B
    unsigned dB = sB0 + lr * 80;
    const unsigned bufstride = 128 * 20 * 4;

    float acc[4][4][4];
    #pragma unroll
    for (int mi = 0; mi < 4; mi++)
        #pragma unroll
        for (int ni = 0; ni < 4; ni++)
            #pragma unroll
            for (int r = 0; r < 4; r++) acc[mi][ni][r] = 0.0f;

    int nk = K >> 4;
    #pragma unroll
    for (int j = 0; j < 2; j++) {
        int s = seg0 + j;
        cp16(dA + s * 16, arow + s * 4, avalid);
        cp16(dB + s * 16, brow + s * 4, true);
    }
    cp_commit();
    int buf = 0;
    for (int i = 0; i < nk; i++) {
        cp_wait0();
        __syncthreads();
        if (i + 1 < nk) {
            int nb = buf ^ 1;
            #pragma unroll
            for (int j = 0; j < 2; j++) {
                int s = seg0 + j;
                cp16(dA + nb * bufstride + s * 16, arow + (i + 1) * 16 + s * 4, avalid);
                cp16(dB + nb * bufstride + s * 16, brow + (i + 1) * 16 + s * 4, true);
            }
            cp_commit();
        }
        const float* Ab = As[buf];
        const float* Bb = Bs[buf];
        #pragma unroll
        for (int kk = 0; kk < 16; kk += 8) {
            unsigned af[4][4];
            #pragma unroll
            for (int mi = 0; mi < 4; mi++) {
                int mb = wm0 + mi * 16 + gid;
                af[mi][0] = f2tf(Ab[mb * 20 + kk + tq]);
                af[mi][1] = f2tf(Ab[(mb + 8) * 20 + kk + tq]);
                af[mi][2] = f2tf(Ab[mb * 20 + kk + tq + 4]);
                af[mi][3] = f2tf(Ab[(mb + 8) * 20 + kk + tq + 4]);
            }
            unsigned bf[4][2];
            #pragma unroll
            for (int ni = 0; ni < 4; ni++) {
                int nb = wn0 + ni * 8 + gid;
                bf[ni][0] = f2tf(Bb[nb * 20 + kk + tq]);
                bf[ni][1] = f2tf(Bb[nb * 20 + kk + tq + 4]);
            }
            #pragma unroll
            for (int mi = 0; mi < 4; mi++)
                #pragma unroll
                for (int ni = 0; ni < 4; ni++)
                    mma_tf32(acc[mi][ni], af[mi], bf[ni]);
        }
        buf ^= 1;
    }
    // epilogue
    #pragma unroll
    for (int mi = 0; mi < 4; mi++) {
        #pragma unroll
        for (int h = 0; h < 2; h++) {
            int rowl = wm0 + mi * 16 + gid + h * 8;
            int m = row0 + rowl;
            if (m >= M) continue;
            int rr = SCATTER_C ? sidx[m] : m;
            #pragma unroll
            for (int ni = 0; ni < 4; ni++) {
                int col = col0 + wn0 + ni * 8 + tq * 2;
                float c0 = acc[mi][ni][h * 2 + 0] + bias[col];
                float c1 = acc[mi][ni][h * 2 + 1] + bias[col + 1];
                if (GELU_EP) {
                    c0 = 0.5f * c0 * (1.0f + erff(c0 * 0.70710678118654752f));
                    c1 = 0.5f * c1 * (1.0f + erff(c1 * 0.70710678118654752f));
                }
                if (RESID) {
                    c0 += resid[(size_t)m * Nc + col];
                    c1 += resid[(size_t)m * Nc + col + 1];
                }
                *(float2*)(C + (size_t)rr * Nc + col) = make_float2(c0, c1);
            }
        }
    }
}

// ================= tf32 implicit-GEMM dilated conv =================
// src NHWC [2,400,400,128]; Wt [o][tap*128+ci] (K=1152); BN + ReLU epilogue.
// Block: 128 pixels x 128 out-channels. 8 warps, 4x2 grid, warp tile 32x64.
__global__ void __launch_bounds__(256) conv_tc(
    const float* __restrict__ src, const float* __restrict__ Wt,
    const float* __restrict__ bng, const float* __restrict__ bnb,
    const float* __restrict__ bnm, const float* __restrict__ bnv,
    float* __restrict__ dst, int nchw)
{
    __shared__ float As[2][128 * 20];
    __shared__ float Bs[2][128 * 20];
    int tid = threadIdx.x;
    int p0 = blockIdx.y * 128;
    int lane = tid & 31, wid = tid >> 5;
    int gid = lane >> 2, tq = lane & 3;
    int wm0 = (wid & 3) * 32;      // 4 m-warps * 32 rows = 128
    int wn0 = (wid >> 2) * 64;     // 2 n-warps * 64 cols = 128

    int lr = tid & 127;
    int seg0 = (tid >> 7) * 2;
    int p = p0 + lr;
    int bb = p / (NY * NX);
    int rem = p % (NY * NX);
    int py = rem / NX, px = rem % NX;
    const float* brow = Wt + (size_t)lr * 1152;
    unsigned sA0 = (unsigned)__cvta_generic_to_shared(&As[0][0]);
    unsigned sB0 = (unsigned)__cvta_generic_to_shared(&Bs[0][0]);
    unsigned dA = sA0 + lr * 80;
    unsigned dB = sB0 + lr * 80;
    const unsigned bufstride = 128 * 20 * 4;

    float acc[2][8][4];
    #pragma unroll
    for (int mi = 0; mi < 2; mi++)
        #pragma unroll
        for (int ni = 0; ni < 8; ni++)
            #pragma unroll
            for (int r = 0; r < 4; r++) acc[mi][ni][r] = 0.0f;

    const int nk = 72;  // 1152/16
    auto issueA = [&](int i, int nb) {
        int tap = i >> 3;
        int dy = (tap / 3 - 1) * 2, dx = (tap % 3 - 1) * 2;
        int yy = py + dy, xx = px + dx;
        bool valid = (unsigned)yy < NY && (unsigned)xx < NX;
        const float* arow = src + (((size_t)bb * NY + (valid ? yy : 0)) * NX + (valid ? xx : 0)) * DIM
                            + ((i & 7) * 16);
        #pragma unroll
        for (int j = 0; j < 2; j++) {
            int s = seg0 + j;
            cp16(dA + nb * bufstride + s * 16, arow + s * 4, valid);
            cp16(dB + nb * bufstride + s * 16, brow + i * 16 + s * 4, true);
        }
    };
    issueA(0, 0);
    cp_commit();
    int buf = 0;
    for (int i = 0; i < nk; i++) {
        cp_wait0();
        __syncthreads();
        if (i + 1 < nk) { issueA(i + 1, buf ^ 1); cp_commit(); }
        const float* Ab = As[buf];
        const float* Bb = Bs[buf];
        #pragma unroll
        for (int kk = 0; kk < 16; kk += 8) {
            unsigned af[2][4];
            #pragma unroll
            for (int mi = 0; mi < 2; mi++) {
                int mb = wm0 + mi * 16 + gid;
                af[mi][0] = f2tf(Ab[mb * 20 + kk + tq]);
                af[mi][1] = f2tf(Ab[(mb + 8) * 20 + kk + tq]);
                af[mi][2] = f2tf(Ab[mb * 20 + kk + tq + 4]);
                af[mi][3] = f2tf(Ab[(mb + 8) * 20 + kk + tq + 4]);
            }
            unsigned bf[8][2];
            #pragma unroll
            for (int ni = 0; ni < 8; ni++) {
                int nb = wn0 + ni * 8 + gid;
                bf[ni][0] = f2tf(Bb[nb * 20 + kk + tq]);
                bf[ni][1] = f2tf(Bb[nb * 20 + kk + tq + 4]);
            }
            #pragma unroll
            for (int mi = 0; mi < 2; mi++)
                #pragma unroll
                for (int ni = 0; ni < 8; ni++)
                    mma_tf32(acc[mi][ni], af[mi], bf[ni]);
        }
        buf ^= 1;
    }
    #pragma unroll
    for (int mi = 0; mi < 2; mi++) {
        #pragma unroll
        for (int h = 0; h < 2; h++) {
            int rowl = wm0 + mi * 16 + gid + h * 8;
            int pp = p0 + rowl;
            int b2 = pp / (NY * NX);
            int r2 = pp % (NY * NX);
            int y2 = r2 / NX, x2 = r2 % NX;
            #pragma unroll
            for (int ni = 0; ni < 8; ni++) {
                int o = wn0 + ni * 8 + tq * 2;
                float sc0 = bng[o] * rsqrtf(bnv[o] + 1e-3f);
                float sc1 = bng[o + 1] * rsqrtf(bnv[o + 1] + 1e-3f);
                float c0 = fmaxf((acc[mi][ni][h * 2 + 0] - bnm[o]) * sc0 + bnb[o], 0.0f);
                float c1 = fmaxf((acc[mi][ni][h * 2 + 1] - bnm[o + 1]) * sc1 + bnb[o + 1], 0.0f);
                if (nchw) {
                    dst[(((size_t)b2 * DIM + o) * NY + y2) * NX + x2] = c0;
                    dst[(((size_t)b2 * DIM + o + 1) * NY + y2) * NX + x2] = c1;
                } else {
                    *(float2*)(dst + (size_t)pp * DIM + o) = make_float2(c0, c1);
                }
            }
        }
    }
}

// ---------------- windowed attention ----------------
__global__ void __launch_bounds__(128) attn_kernel(
    const float* __restrict__ QK, const float* __restrict__ V,
    float* __restrict__ O, int M, int cap)
{
    __shared__ float Ks[100 * 16];
    __shared__ float Vs[100 * 16];
    __shared__ float sred[4][32][16];
    int w = blockIdx.x, h = blockIdx.y;
    int base = w * cap;
    int nval = min(cap, M - base);
    int tid = threadIdx.x, lane = tid & 31, warp = tid >> 5;
    for (int i = tid; i < nval * 16; i += 128) {
        int t = i >> 4, d = i & 15;
        Ks[t * 16 + d] = QK[(size_t)(base + t) * 256 + 128 + h * 16 + d];
        Vs[t * 16 + d] = V[(size_t)(base + t) * 128 + h * 16 + d];
    }
    __syncthreads();
    for (int r = warp; r < nval; r += 4) {
        float q[16];
        #pragma unroll
        for (int d = 0; d < 16; d++) q[d] = QK[(size_t)(base + r) * 256 + h * 16 + d];
        float s[4];
        float mx = -1e30f;
        #pragma unroll
        for (int jj = 0; jj < 4; jj++) {
            int key = lane + jj * 32;
            float sc = -1e30f;
            if (key < nval) {
                sc = 0.0f;
                #pragma unroll
                for (int d = 0; d < 16; d++) sc += q[d] * Ks[key * 16 + d];
                sc *= 0.25f;
            }
            s[jj] = sc;
            mx = fmaxf(mx, sc);
        }
        #pragma unroll
        for (int o = 16; o; o >>= 1) mx = fmaxf(mx, __shfl_xor_sync(0xffffffffu, mx, o));
        float l = 0.0f;
        float acc[16] = {};
        #pragma unroll
        for (int jj = 0; jj < 4; jj++) {
            int key = lane + jj * 32;
            if (key < nval) {
                float pexp = __expf(s[jj] - mx);
                l += pexp;
                #pragma unroll
                for (int d = 0; d < 16; d++) acc[d] += pexp * Vs[key * 16 + d];
            }
        }
        #pragma unroll
        for (int o = 16; o; o >>= 1) l += __shfl_xor_sync(0xffffffffu, l, o);
        #pragma unroll
        for (int d = 0; d < 16; d++) sred[warp][lane][d] = acc[d];
        __syncwarp();
        if (lane < 16) {
            float o = 0.0f;
            #pragma unroll
            for (int l2 = 0; l2 < 32; l2++) o += sred[warp][l2][lane];
            O[(size_t)(base + r) * 128 + h * 16 + lane] = o / l;
        }
        __syncwarp();
    }
}

// ---------------- layernorm ----------------
__global__ void __launch_bounds__(256) ln_kernel(
    const float* __restrict__ X, const float* __restrict__ X2,
    const float* __restrict__ g, const float* __restrict__ b,
    float* __restrict__ Y, int M)
{
    int row = blockIdx.x * 8 + (threadIdx.x >> 5);
    if (row >= M) return;
    int lane = threadIdx.x & 31;
    float v[4];
    #pragma unroll
    for (int i = 0; i < 4; i++) {
        int c = lane + i * 32;
        float t = X[(size_t)row * DIM + c];
        if (X2) t += X2[(size_t)row * DIM + c];
        v[i] = t;
    }
    float s = v[0] + v[1] + v[2] + v[3];
    #pragma unroll
    for (int o = 16; o; o >>= 1) s += __shfl_xor_sync(0xffffffffu, s, o);
    float mu = s * (1.0f / 128.0f);
    float vs = 0.0f;
    #pragma unroll
    for (int i = 0; i < 4; i++) { float d = v[i] - mu; vs += d * d; }
    #pragma unroll
    for (int o = 16; o; o >>= 1) vs += __shfl_xor_sync(0xffffffffu, vs, o);
    float inv = rsqrtf(vs * (1.0f / 128.0f) + 1e-5f);
    #pragma unroll
    for (int i = 0; i < 4; i++) {
        int c = lane + i * 32;
        Y[(size_t)row * DIM + c] = (v[i] - mu) * inv * g[c] + b[c];
    }
}

// ---------------- BEV scatter ----------------
__global__ void scatter_kernel(const float* __restrict__ feat,
                               const int* __restrict__ coors,
                               float* __restrict__ canvas)
{
    int i = blockIdx.x;
    int c = threadIdx.x;
    int b = coors[i * 4 + 0];
    int y = coors[i * 4 + 2];
    int x = coors[i * 4 + 3];
    canvas[(((size_t)b * NY + y) * NX + x) * DIM + c] = feat[(size_t)i * DIM + c];
}

// conv weight: [cv][o][ci][ky][kx] -> [cv][o][(ky*3+kx)*128+ci]
__global__ void prep_wt_kernel(const float* __restrict__ cw, float* __restrict__ wt) {
    int idx = blockIdx.x * 256 + threadIdx.x;
    if (idx >= 2 * 128 * 1152) return;
    int cv = idx / (128 * 1152);
    int r = idx % (128 * 1152);
    int o = r / 1152, k = r % 1152;
    int tap = k / 128, ci = k % 128;
    int ky = tap / 3, kx = tap % 3;
    wt[idx] = cw[((((size_t)cv * DIM + o) * DIM + ci) * 3 + ky) * 3 + kx];
}

// ---------------- host launcher ----------------
static inline dim3 ggrid(int M, int Nc) { return dim3(Nc / 128, (M + 127) / 128); }

extern "C" void kernel_launch(void* const* d_in, const int* in_sizes, int n_in,
                              void* d_out, int out_size) {
    const float* voxel_feat = (const float*)d_in[0];
    const int*   coors      = (const int*)d_in[1];
    const float* ciw0       = (const float*)d_in[2];
    const float* ciw1       = (const float*)d_in[3];
    const int*   vx00       = (const int*)d_in[4];
    const int*   vx01       = (const int*)d_in[6];
    const int*   vx10       = (const int*)d_in[8];
    const int*   vx11       = (const int*)d_in[10];
    const float* ipw        = (const float*)d_in[12];
    const float* ipb        = (const float*)d_in[13];
    const float* ow         = (const float*)d_in[14];
    const float* ob         = (const float*)d_in[15];
    const float* l1w        = (const float*)d_in[16];
    const float* l1b        = (const float*)d_in[17];
    const float* l2w        = (const float*)d_in[18];
    const float* l2b        = (const float*)d_in[19];
    const float* g1         = (const float*)d_in[20];
    const float* b1         = (const float*)d_in[21];
    const float* g2         = (const float*)d_in[22];
    const float* b2         = (const float*)d_in[23];
    const float* cw         = (const float*)d_in[24];
    const float* bng        = (const float*)d_in[25];
    const float* bnb        = (const float*)d_in[26];
    const float* bnm        = (const float*)d_in[27];
    const float* bnv        = (const float*)d_in[28];

    int ntok0  = in_sizes[4];
    int ntok1  = in_sizes[6];
    int ntok0b = in_sizes[8];
    int ntok1b = in_sizes[10];

    float *feat, *fp, *pos, *qk, *val, *oatt, *attn, *hbuf, *tmp, *canvas, *conv1, *wt;
    cudaGetSymbolAddress((void**)&feat,   g_feat);
    cudaGetSymbolAddress((void**)&fp,     g_fp);
    cudaGetSymbolAddress((void**)&pos,    g_pos);
    cudaGetSymbolAddress((void**)&qk,     g_qk);
    cudaGetSymbolAddress((void**)&val,    g_val);
    cudaGetSymbolAddress((void**)&oatt,   g_oatt);
    cudaGetSymbolAddress((void**)&attn,   g_attn);
    cudaGetSymbolAddress((void**)&hbuf,   g_hbuf);
    cudaGetSymbolAddress((void**)&tmp,    g_tmp);
    cudaGetSymbolAddress((void**)&canvas, g_canvas);
    cudaGetSymbolAddress((void**)&conv1,  g_conv1);
    cudaGetSymbolAddress((void**)&wt,     g_wt);

    cudaMemcpyAsync(feat, voxel_feat, (size_t)NTOK * DIM * sizeof(float),
                    cudaMemcpyDeviceToDevice);
    pos_kernel<<<NTOK, 128>>>(ciw0, pos);
    pos_kernel<<<NTOK, 128>>>(ciw1, pos + (size_t)NTOK * DIM);
    prep_wt_kernel<<<(2 * 128 * 1152 + 255) / 256, 256>>>(cw, wt);

    for (int li = 0; li < NLAYER; li++) {
        int s = li & 1;
        const int* vv[2];
        int mm[2];
        if (s == 0) { vv[0] = vx00; vv[1] = vx01; mm[0] = ntok0;  mm[1] = ntok1; }
        else        { vv[0] = vx10; vv[1] = vx11; mm[0] = ntok0b; mm[1] = ntok1b; }
        int caps[2] = {25, 100};
        const float* posS = pos + (size_t)s * NTOK * DIM;
        const float* Wip  = ipw + (size_t)li * 384 * DIM;
        const float* Bip  = ipb + (size_t)li * 384;

        addpos_kernel<<<NTOK * DIM / 4 / 256, 256>>>(feat, posS, fp);

        for (int lvl = 0; lvl < 2; lvl++) {
            int M = mm[lvl];
            const int* v = vv[lvl];
            gemm_tc<true, false, false, false><<<ggrid(M, 256), 256>>>(
                fp, v, Wip, Bip, nullptr, nullptr, qk, M, 128, 256);
            gemm_tc<true, false, false, false><<<ggrid(M, 128), 256>>>(
                feat, v, Wip + 256 * 128, Bip + 256, nullptr, nullptr, val, M, 128, 128);
            int nw = (M + caps[lvl] - 1) / caps[lvl];
            attn_kernel<<<dim3(nw, NHEAD), 128>>>(qk, val, oatt, M, caps[lvl]);
            gemm_tc<false, false, false, true><<<ggrid(M, 128), 256>>>(
                oatt, nullptr, ow + (size_t)li * 128 * 128, ob + (size_t)li * 128,
                nullptr, v, attn, M, 128, 128);
        }
        ln_kernel<<<(NTOK + 7) / 8, 256>>>(feat, attn, g1 + li * 128, b1 + li * 128,
                                           feat, NTOK);
        gemm_tc<false, true, false, false><<<ggrid(NTOK, 256), 256>>>(
            feat, nullptr, l1w + (size_t)li * DFF * DIM, l1b + (size_t)li * DFF,
            nullptr, nullptr, hbuf, NTOK, 128, 256);
        gemm_tc<false, false, true, false><<<ggrid(NTOK, 128), 256>>>(
            hbuf, nullptr, l2w + (size_t)li * DIM * DFF, l2b + (size_t)li * DIM,
            feat, nullptr, tmp, NTOK, 256, 128);
        ln_kernel<<<(NTOK + 7) / 8, 256>>>(tmp, nullptr, g2 + li * 128, b2 + li * 128,
                                           feat, NTOK);
    }

    cudaMemsetAsync(canvas, 0, (size_t)NPIX * DIM * sizeof(float));
    scatter_kernel<<<NTOK, 128>>>(feat, coors, canvas);
    conv_tc<<<dim3(1, NPIX / 128), 256>>>(canvas, wt, bng, bnb, bnm, bnv, conv1, 0);
    conv_tc<<<dim3(1, NPIX / 128), 256>>>(conv1, wt + 128 * 1152, bng + 128, bnb + 128,
                                          bnm + 128, bnv + 128, (float*)d_out, 1);
}